// round 9
// baseline (speedup 1.0000x reference)
#include <cuda_runtime.h>
#include <cuda_bf16.h>
#include <cuda_fp16.h>
#include <cstdint>

// ---------------- dims ----------------
#define B_    16
#define C_    256
#define O_    256
#define HW_   56
#define NPIX  3136
#define NK    8
#define HID   64
#define KTOT  2304
#define NKEL  589824
#define PSTR  3264          // NPIX + 128 (64 guard each side)
#define GUARD 64

#define KC     64
#define NCHUNK 36           // 4 ic-groups * 9 taps
#define GRIDX  25           // ceil(3136/128) pix tiles
#define NSTG   3

// conv smem (fp16 units)
#define SW_ROW   72
#define SX_ROW   136
#define SW_STG   (128 * SW_ROW)               // 9216
#define SX_STG   (64 * SX_ROW)                // 8704
#define STG_ELEMS (SW_STG + SX_STG)           // 17920
#define SMEM_BYTES (NSTG * STG_ELEMS * 2)     // 107520

// mega-kernel smem (floats): sv[8*KTOT] sal[128] sp[4096] sh[1024] sc[128]
#define MEGA_FLOATS (8 * KTOT + 128 + B_ * C_ + B_ * HID + B_ * NK)
#define MEGA_SMEM   (MEGA_FLOATS * 4 + 256)

__device__ float g_pooled[B_ * C_];
__device__ __align__(16) unsigned short g_wmix[(size_t)B_ * O_ * KTOT];
#define NPLANES ((size_t)B_ * 3 * C_)
__device__ __align__(16) unsigned short g_xs[NPLANES * PSTR + 64];

// ---------------- asm helpers ----------------
__device__ __forceinline__ uint32_t smem_u32(const void* p) {
    uint32_t a;
    asm("{ .reg .u64 t; cvta.to.shared.u64 t, %1; cvt.u32.u64 %0, t; }" : "=r"(a) : "l"(p));
    return a;
}
#define CP16(dst, src) asm volatile("cp.async.cg.shared.global [%0], [%1], 16;" :: "r"(dst), "l"(src))
#define CP_COMMIT()    asm volatile("cp.async.commit_group;" ::: "memory")
#define CP_WAIT(n)     asm volatile("cp.async.wait_group %0;" :: "n"(n) : "memory")

__device__ __forceinline__ void ldsm4(uint32_t* r, uint32_t a) {
    asm volatile("ldmatrix.sync.aligned.m8n8.x4.shared.b16 {%0,%1,%2,%3}, [%4];"
                 : "=r"(r[0]), "=r"(r[1]), "=r"(r[2]), "=r"(r[3]) : "r"(a));
}
__device__ __forceinline__ void ldsm4t(uint32_t* r, uint32_t a) {
    asm volatile("ldmatrix.sync.aligned.m8n8.x4.trans.shared.b16 {%0,%1,%2,%3}, [%4];"
                 : "=r"(r[0]), "=r"(r[1]), "=r"(r[2]), "=r"(r[3]) : "r"(a));
}
__device__ __forceinline__ void mma_f16(float* d, const uint32_t* a, const uint32_t* b) {
    asm volatile("mma.sync.aligned.m16n8k16.row.col.f32.f16.f16.f32 "
                 "{%0,%1,%2,%3}, {%4,%5,%6,%7}, {%8,%9}, {%0,%1,%2,%3};"
                 : "+f"(d[0]), "+f"(d[1]), "+f"(d[2]), "+f"(d[3])
                 : "r"(a[0]), "r"(a[1]), "r"(a[2]), "r"(a[3]), "r"(b[0]), "r"(b[1]));
}
__device__ __forceinline__ uint32_t h2u(float a, float b) {
    __half2 h = __floats2half2_rn(a, b);
    return *(uint32_t*)&h;
}

// ---------------- Kernel 1: global average pool ----------------
__global__ void pool_kernel(const float* __restrict__ x) {
    int c = blockIdx.x, b = blockIdx.y;
    const float4* p = (const float4*)(x + ((size_t)(b * C_ + c)) * NPIX);
    float s = 0.f;
    for (int i = threadIdx.x; i < NPIX / 4; i += 256) {
        float4 v = p[i];
        s += (v.x + v.y) + (v.z + v.w);
    }
    __shared__ float red[8];
    #pragma unroll
    for (int o = 16; o > 0; o >>= 1) s += __shfl_xor_sync(0xffffffffu, s, o);
    if ((threadIdx.x & 31) == 0) red[threadIdx.x >> 5] = s;
    __syncthreads();
    if (threadIdx.x < 8) {
        s = red[threadIdx.x];
        #pragma unroll
        for (int o = 4; o > 0; o >>= 1) s += __shfl_xor_sync(0xffu, s, o);
        if (threadIdx.x == 0) g_pooled[b * C_ + c] = s * (1.0f / NPIX);
    }
}

// ---------------- Kernel 2: MEGA — (MLP+mix) blocks 0..255  ||  planes blocks 256+ ----
extern __shared__ float megasm[];
__global__ void __launch_bounds__(512)
mega_kernel(const float* __restrict__ x, const float* __restrict__ kern,
            const float* __restrict__ w1, const float* __restrict__ b1,
            const float* __restrict__ w2, const float* __restrict__ b2) {
    const int tid = threadIdx.x;

    if (blockIdx.x < 256) {
        // ======== MLP (redundant per block, deterministic) + weight mix ========
        float* sv  = megasm;                 // [8][KTOT]
        float* sal = sv + 8 * KTOT;          // [128]
        float* sp  = sal + 128;              // [B_*C_]
        float* sh  = sp + B_ * C_;           // [B_*HID]
        float* sc  = sh + B_ * HID;          // [B_*NK]
        const int o = blockIdx.x;

        // start sv loads (independent of MLP)
        #pragma unroll
        for (int k = 0; k < 8; k++)
            for (int i = tid; i < KTOT; i += 512)
                sv[k * KTOT + i] = kern[(size_t)k * NKEL + (size_t)o * KTOT + i];

        for (int i = tid; i < B_ * C_; i += 512) sp[i] = g_pooled[i];
        __syncthreads();
        for (int t = tid; t < B_ * HID; t += 512) {
            int b = t >> 6, j = t & 63;
            float s = b1[j];
            #pragma unroll 8
            for (int c = 0; c < C_; c++) s = fmaf(sp[b * C_ + c], w1[c * HID + j], s);
            sh[t] = fmaxf(s, 0.f);
        }
        __syncthreads();
        if (tid < B_ * NK) {
            int b = tid >> 3, k = tid & 7;
            float s = b2[k];
            #pragma unroll
            for (int j = 0; j < HID; j++) s = fmaf(sh[b * HID + j], w2[j * NK + k], s);
            sc[tid] = s;
        }
        __syncthreads();
        if (tid < B_) {
            float m = -1e30f;
            #pragma unroll
            for (int k = 0; k < NK; k++) m = fmaxf(m, sc[tid * NK + k]);
            float e[NK], sum = 0.f;
            #pragma unroll
            for (int k = 0; k < NK; k++) { e[k] = __expf(sc[tid * NK + k] - m); sum += e[k]; }
            float inv = 1.0f / sum;
            #pragma unroll
            for (int k = 0; k < NK; k++) sal[tid * NK + k] = e[k] * inv;
        }
        __syncthreads();

        for (int kp0 = tid * 2; kp0 < KTOT; kp0 += 1024) {
            int i0 = ((kp0 & 255) * 9) + (kp0 >> 8);
            int i1 = (((kp0 + 1) & 255) * 9) + ((kp0 + 1) >> 8);
            float v0[8], v1[8];
            #pragma unroll
            for (int k = 0; k < 8; k++) { v0[k] = sv[k * KTOT + i0]; v1[k] = sv[k * KTOT + i1]; }
            #pragma unroll
            for (int b = 0; b < B_; b++) {
                float s0 = 0.f, s1 = 0.f;
                #pragma unroll
                for (int k = 0; k < 8; k++) {
                    float a = sal[b * NK + k];
                    s0 = fmaf(a, v0[k], s0);
                    s1 = fmaf(a, v1[k], s1);
                }
                ((uint32_t*)g_wmix)[(((size_t)(b * O_ + o)) * KTOT + kp0) >> 1] = h2u(s0, s1);
            }
        }
    } else {
        // ======== planes: unit = (b, ic) ========
        const int u = blockIdx.x - 256;
        const int ic = u & 255, b = u >> 8;
        const float* xp = x + ((size_t)(b * C_ + ic)) * NPIX;

        for (int g = tid; g < NPIX / 8; g += 512) {
            int p0 = g * 8;
            int w0 = p0 % HW_;
            float4 a0 = *(const float4*)(xp + p0);
            float4 a1 = *(const float4*)(xp + p0 + 4);
            float L  = (w0 > 0)       ? xp[p0 - 1] : 0.f;
            float Rv = (w0 + 8 < HW_) ? xp[p0 + 8] : 0.f;
            float c0[8] = {a0.x, a0.y, a0.z, a0.w, a1.x, a1.y, a1.z, a1.w};

            uint4 v1 = make_uint4(h2u(c0[0], c0[1]), h2u(c0[2], c0[3]),
                                  h2u(c0[4], c0[5]), h2u(c0[6], c0[7]));
            uint4 v0 = make_uint4(h2u(L, c0[0]), h2u(c0[1], c0[2]),
                                  h2u(c0[3], c0[4]), h2u(c0[5], c0[6]));
            uint4 v2 = make_uint4(h2u(c0[1], c0[2]), h2u(c0[3], c0[4]),
                                  h2u(c0[5], c0[6]), h2u(c0[7], Rv));

            *(uint4*)&g_xs[(size_t)((b * 3 + 0) * C_ + ic) * PSTR + GUARD + p0] = v0;
            *(uint4*)&g_xs[(size_t)((b * 3 + 1) * C_ + ic) * PSTR + GUARD + p0] = v1;
            *(uint4*)&g_xs[(size_t)((b * 3 + 2) * C_ + ic) * PSTR + GUARD + p0] = v2;
        }
        if (tid < 48) {
            int dwi = tid / 16, q = tid % 16;
            int pos = (q < 8) ? q * 8 : (PSTR - 128 + (q - 8) * 8 + 64);
            *(uint4*)&g_xs[(size_t)((b * 3 + dwi) * C_ + ic) * PSTR + pos] = make_uint4(0, 0, 0, 0);
        }
        if (u == 0 && tid < 8)
            *(uint4*)&g_xs[NPLANES * PSTR + tid * 8] = make_uint4(0, 0, 0, 0);
    }
}

// ---------------- Kernel 3: implicit-GEMM conv via mma.sync (fp16, KC=64) --------
extern __shared__ __align__(16) unsigned short dynsm[];

__global__ void __launch_bounds__(256, 2)
conv_kernel(float* __restrict__ out) {
    const int tid = threadIdx.x;
    const int n0 = blockIdx.x * 128;
    const int o0 = blockIdx.y * 128;
    const int bb = blockIdx.z;

    const int warp = tid >> 5, L = tid & 31;
    const int wo = (warp >> 2) << 6;
    const int wp = (warp & 3) << 5;
    const int gid = L >> 2, tid4 = L & 3;

    const uint32_t sbase = smem_u32(dynsm);
    const int aRow = wo + (L & 15);
    const int aCol = (L >> 4) << 3;
    const int xRow = L & 15;
    const int xCol = wp + ((L >> 4) << 3);

    int wRow[4], wJ[4], xKK[4], xJ[4];
    #pragma unroll
    for (int i = 0; i < 4; i++) {
        int e = tid + i * 256;
        wRow[i] = e >> 3; wJ[i] = e & 7;
        xKK[i] = e >> 4; xJ[i] = e & 15;
    }

    float acc[4][4][4];
    #pragma unroll
    for (int mt = 0; mt < 4; mt++)
        #pragma unroll
        for (int nt = 0; nt < 4; nt++)
            #pragma unroll
            for (int r = 0; r < 4; r++) acc[mt][nt][r] = 0.f;

    auto load_chunk = [&](int c, int stg) {
        int icg = c / 9;
        int tap = c - icg * 9;
        int dwi = tap % 3;
        int dh56 = (tap / 3 - 1) * HW_;
        uint32_t sb = sbase + (uint32_t)stg * (STG_ELEMS * 2);
        #pragma unroll
        for (int i = 0; i < 4; i++) {
            const unsigned short* srcw = g_wmix
                + ((size_t)(bb * O_ + o0 + wRow[i])) * KTOT
                + tap * 256 + icg * 64 + wJ[i] * 8;
            CP16(sb + 2u * (wRow[i] * SW_ROW + wJ[i] * 8), srcw);
            size_t plane = (size_t)((bb * 3 + dwi) * C_ + icg * 64 + xKK[i]);
            const unsigned short* srcx = g_xs + plane * PSTR + GUARD + n0 + dh56 + xJ[i] * 8;
            CP16(sb + 2u * (SW_STG + xKK[i] * SX_ROW + xJ[i] * 8), srcx);
        }
    };

    load_chunk(0, 0); CP_COMMIT();
    load_chunk(1, 1); CP_COMMIT();

    int stage = 0;
    for (int c = 0; c < NCHUNK; c++) {
        if (c < NCHUNK - 1) { CP_WAIT(1); } else { CP_WAIT(0); }
        __syncthreads();
        if (c + 2 < NCHUNK) {
            int s2 = stage + 2; if (s2 >= NSTG) s2 -= NSTG;
            load_chunk(c + 2, s2);
            CP_COMMIT();
        }

        const uint32_t sb = sbase + (uint32_t)stage * (STG_ELEMS * 2);
        #pragma unroll
        for (int ks = 0; ks < 4; ks++) {
            uint32_t A[4][4], Bh[2][4];
            #pragma unroll
            for (int mt = 0; mt < 4; mt++) {
                uint32_t a = sb + 2u * ((aRow + mt * 16) * SW_ROW + ks * 16 + aCol);
                ldsm4(A[mt], a);
            }
            #pragma unroll
            for (int np = 0; np < 2; np++) {
                uint32_t a = sb + 2u * (SW_STG + (ks * 16 + xRow) * SX_ROW + xCol + np * 16);
                ldsm4t(Bh[np], a);
            }
            #pragma unroll
            for (int mt = 0; mt < 4; mt++)
                #pragma unroll
                for (int nt = 0; nt < 4; nt++)
                    mma_f16(acc[mt][nt], A[mt], &Bh[nt >> 1][(nt & 1) * 2]);
        }
        stage = stage + 1; if (stage >= NSTG) stage -= NSTG;
    }

    #pragma unroll
    for (int mt = 0; mt < 4; mt++) {
        #pragma unroll
        for (int nt = 0; nt < 4; nt++) {
            int o = o0 + wo + mt * 16 + gid;
            int pix = n0 + wp + nt * 8 + tid4 * 2;
            if (pix < NPIX) {
                size_t base = ((size_t)(bb * O_ + o)) * NPIX + pix;
                *(float2*)&out[base] = make_float2(acc[mt][nt][0], acc[mt][nt][1]);
                *(float2*)&out[base + (size_t)8 * NPIX] = make_float2(acc[mt][nt][2], acc[mt][nt][3]);
            }
        }
    }
}

extern "C" void kernel_launch(void* const* d_in, const int* in_sizes, int n_in,
                              void* d_out, int out_size) {
    const float* x    = (const float*)d_in[0];
    const float* kern = (const float*)d_in[1];
    const float* w1   = (const float*)d_in[2];
    const float* b1   = (const float*)d_in[3];
    const float* w2   = (const float*)d_in[4];
    const float* b2   = (const float*)d_in[5];
    float* out = (float*)d_out;

    cudaFuncSetAttribute(conv_kernel, cudaFuncAttributeMaxDynamicSharedMemorySize, SMEM_BYTES);
    cudaFuncSetAttribute(mega_kernel, cudaFuncAttributeMaxDynamicSharedMemorySize, MEGA_SMEM);

    pool_kernel<<<dim3(C_, B_), 256>>>(x);
    mega_kernel<<<256 + B_ * C_, 512, MEGA_SMEM>>>(x, kern, w1, b1, w2, b2);
    conv_kernel<<<dim3(GRIDX, 2, B_), 256, SMEM_BYTES>>>(out);
}

// round 10
// speedup vs baseline: 1.1042x; 1.1042x over previous
#include <cuda_runtime.h>
#include <cuda_bf16.h>
#include <cuda_fp16.h>
#include <cstdint>

// ---------------- dims ----------------
#define B_    16
#define C_    256
#define O_    256
#define HW_   56
#define NPIX  3136
#define NK    8
#define HID   64
#define KTOT  2304
#define NKEL  589824
#define PSTR  3264          // NPIX + 128 (64 guard each side)
#define GUARD 64

#define KC     64
#define NCHUNK 36           // 4 ic-groups * 9 taps
#define GRIDX  25           // ceil(3136/128) pix tiles
#define NSTG   3

// conv smem (fp16 units)
#define SW_ROW   72
#define SX_ROW   136
#define SW_STG   (128 * SW_ROW)               // 9216
#define SX_STG   (64 * SX_ROW)                // 8704
#define STG_ELEMS (SW_STG + SX_STG)           // 17920
#define SMEM_BYTES (NSTG * STG_ELEMS * 2)     // 107520
#define MIX_SMEM  (8 * KTOT * 4 + 512)        // 74240

__device__ float g_pooled[B_ * C_];
__device__ float g_alphas[B_ * NK];
__device__ __align__(16) unsigned short g_wmix[(size_t)B_ * O_ * KTOT];
#define NPLANES ((size_t)B_ * 3 * C_)
__device__ __align__(16) unsigned short g_xs[NPLANES * PSTR + 64];

// ---------------- asm helpers ----------------
__device__ __forceinline__ uint32_t smem_u32(const void* p) {
    uint32_t a;
    asm("{ .reg .u64 t; cvta.to.shared.u64 t, %1; cvt.u32.u64 %0, t; }" : "=r"(a) : "l"(p));
    return a;
}
#define CP16(dst, src) asm volatile("cp.async.cg.shared.global [%0], [%1], 16;" :: "r"(dst), "l"(src))
#define CP_COMMIT()    asm volatile("cp.async.commit_group;" ::: "memory")
#define CP_WAIT(n)     asm volatile("cp.async.wait_group %0;" :: "n"(n) : "memory")

__device__ __forceinline__ void ldsm4(uint32_t* r, uint32_t a) {
    asm volatile("ldmatrix.sync.aligned.m8n8.x4.shared.b16 {%0,%1,%2,%3}, [%4];"
                 : "=r"(r[0]), "=r"(r[1]), "=r"(r[2]), "=r"(r[3]) : "r"(a));
}
__device__ __forceinline__ void ldsm4t(uint32_t* r, uint32_t a) {
    asm volatile("ldmatrix.sync.aligned.m8n8.x4.trans.shared.b16 {%0,%1,%2,%3}, [%4];"
                 : "=r"(r[0]), "=r"(r[1]), "=r"(r[2]), "=r"(r[3]) : "r"(a));
}
__device__ __forceinline__ void mma_f16(float* d, const uint32_t* a, const uint32_t* b) {
    asm volatile("mma.sync.aligned.m16n8k16.row.col.f32.f16.f16.f32 "
                 "{%0,%1,%2,%3}, {%4,%5,%6,%7}, {%8,%9}, {%0,%1,%2,%3};"
                 : "+f"(d[0]), "+f"(d[1]), "+f"(d[2]), "+f"(d[3])
                 : "r"(a[0]), "r"(a[1]), "r"(a[2]), "r"(a[3]), "r"(b[0]), "r"(b[1]));
}
__device__ __forceinline__ uint32_t h2u(float a, float b) {
    __half2 h = __floats2half2_rn(a, b);
    return *(uint32_t*)&h;
}

// ---------------- Kernel 1: x -> fp16 planes + pool, register/L1 path ----------
__global__ void __launch_bounds__(256)
split_pool_kernel(const float* __restrict__ x) {
    const int ic = blockIdx.x, b = blockIdx.y;
    const float* xp = x + ((size_t)(b * C_ + ic)) * NPIX;
    __shared__ float red[8];
    float s = 0.f;

    // 392 8-pixel groups, stride 256 (groups never cross rows: 8 | 56... 56/8=7)
    for (int g = threadIdx.x; g < NPIX / 8; g += 256) {
        int p0 = g * 8;
        int w0 = p0 % HW_;
        float4 a0 = *(const float4*)(xp + p0);
        float4 a1 = *(const float4*)(xp + p0 + 4);
        float L  = (w0 > 0)       ? __ldg(xp + p0 - 1) : 0.f;
        float Rv = (w0 + 8 < HW_) ? __ldg(xp + p0 + 8) : 0.f;
        float c0[8] = {a0.x, a0.y, a0.z, a0.w, a1.x, a1.y, a1.z, a1.w};
        s += ((c0[0] + c0[1]) + (c0[2] + c0[3])) + ((c0[4] + c0[5]) + (c0[6] + c0[7]));

        uint4 v1 = make_uint4(h2u(c0[0], c0[1]), h2u(c0[2], c0[3]),
                              h2u(c0[4], c0[5]), h2u(c0[6], c0[7]));
        uint4 v0 = make_uint4(h2u(L, c0[0]), h2u(c0[1], c0[2]),
                              h2u(c0[3], c0[4]), h2u(c0[5], c0[6]));
        uint4 v2 = make_uint4(h2u(c0[1], c0[2]), h2u(c0[3], c0[4]),
                              h2u(c0[5], c0[6]), h2u(c0[7], Rv));

        *(uint4*)&g_xs[(size_t)((b * 3 + 0) * C_ + ic) * PSTR + GUARD + p0] = v0;
        *(uint4*)&g_xs[(size_t)((b * 3 + 1) * C_ + ic) * PSTR + GUARD + p0] = v1;
        *(uint4*)&g_xs[(size_t)((b * 3 + 2) * C_ + ic) * PSTR + GUARD + p0] = v2;
    }

    // pool reduction
    #pragma unroll
    for (int o = 16; o > 0; o >>= 1) s += __shfl_xor_sync(0xffffffffu, s, o);
    if ((threadIdx.x & 31) == 0) red[threadIdx.x >> 5] = s;
    __syncthreads();
    if (threadIdx.x < 8) {
        s = red[threadIdx.x];
        #pragma unroll
        for (int o = 4; o > 0; o >>= 1) s += __shfl_xor_sync(0xffu, s, o);
        if (threadIdx.x == 0) g_pooled[b * C_ + ic] = s * (1.0f / NPIX);
    }

    // guards: 3 planes x (64 front + 64 back) -> 48 uint4
    if (threadIdx.x < 48) {
        int dwi = threadIdx.x / 16, q = threadIdx.x % 16;
        int pos = (q < 8) ? q * 8 : (PSTR - 128 + (q - 8) * 8 + 64);
        *(uint4*)&g_xs[(size_t)((b * 3 + dwi) * C_ + ic) * PSTR + pos] = make_uint4(0, 0, 0, 0);
    }
    if (b == 0 && ic == 0 && threadIdx.x < 8)
        *(uint4*)&g_xs[NPLANES * PSTR + threadIdx.x * 8] = make_uint4(0, 0, 0, 0);
}

// ---------------- Kernel 2: MLP + softmax ----------------
__global__ void mlp_kernel(const float* __restrict__ w1, const float* __restrict__ b1,
                           const float* __restrict__ w2, const float* __restrict__ b2) {
    __shared__ float sp[B_ * C_];
    __shared__ float sh[B_ * HID];
    __shared__ float sc[B_ * NK];
    int tid = threadIdx.x;
    for (int i = tid; i < B_ * C_; i += 256) sp[i] = g_pooled[i];
    __syncthreads();
    for (int t = tid; t < B_ * HID; t += 256) {
        int b = t >> 6, j = t & 63;
        float s = b1[j];
        #pragma unroll 8
        for (int c = 0; c < C_; c++) s = fmaf(sp[b * C_ + c], w1[c * HID + j], s);
        sh[t] = fmaxf(s, 0.f);
    }
    __syncthreads();
    if (tid < B_ * NK) {
        int b = tid >> 3, k = tid & 7;
        float s = b2[k];
        #pragma unroll
        for (int j = 0; j < HID; j++) s = fmaf(sh[b * HID + j], w2[j * NK + k], s);
        sc[tid] = s;
    }
    __syncthreads();
    if (tid < B_) {
        float m = -1e30f;
        #pragma unroll
        for (int k = 0; k < NK; k++) m = fmaxf(m, sc[tid * NK + k]);
        float e[NK], sum = 0.f;
        #pragma unroll
        for (int k = 0; k < NK; k++) { e[k] = __expf(sc[tid * NK + k] - m); sum += e[k]; }
        float inv = 1.0f / sum;
        #pragma unroll
        for (int k = 0; k < NK; k++) g_alphas[tid * NK + k] = e[k] * inv;
    }
}

// ---------------- Kernel 3: weight mixing, smem-staged, coalesced ----------------
extern __shared__ float mixsm[];
__global__ void mix_kernel(const float* __restrict__ kern) {
    float* sv = mixsm;                    // [8][KTOT]
    float* sal = mixsm + 8 * KTOT;        // [128]
    const int o = blockIdx.x, tid = threadIdx.x;
    if (tid < B_ * NK) sal[tid] = g_alphas[tid];
    #pragma unroll
    for (int k = 0; k < 8; k++)
        for (int i = tid; i < KTOT; i += 256)
            sv[k * KTOT + i] = kern[(size_t)k * NKEL + (size_t)o * KTOT + i];
    __syncthreads();

    for (int kp0 = tid * 2; kp0 < KTOT; kp0 += 512) {
        int i0 = ((kp0 & 255) * 9) + (kp0 >> 8);
        int i1 = (((kp0 + 1) & 255) * 9) + ((kp0 + 1) >> 8);
        float v0[8], v1[8];
        #pragma unroll
        for (int k = 0; k < 8; k++) { v0[k] = sv[k * KTOT + i0]; v1[k] = sv[k * KTOT + i1]; }
        #pragma unroll
        for (int b = 0; b < B_; b++) {
            float s0 = 0.f, s1 = 0.f;
            #pragma unroll
            for (int k = 0; k < 8; k++) {
                float a = sal[b * NK + k];
                s0 = fmaf(a, v0[k], s0);
                s1 = fmaf(a, v1[k], s1);
            }
            ((uint32_t*)g_wmix)[(((size_t)(b * O_ + o)) * KTOT + kp0) >> 1] = h2u(s0, s1);
        }
    }
}

// ---------------- Kernel 4: implicit-GEMM conv via mma.sync (fp16, KC=64) --------
extern __shared__ __align__(16) unsigned short dynsm[];

__global__ void __launch_bounds__(256, 2)
conv_kernel(float* __restrict__ out) {
    const int tid = threadIdx.x;
    const int n0 = blockIdx.x * 128;
    const int o0 = blockIdx.y * 128;
    const int bb = blockIdx.z;

    const int warp = tid >> 5, L = tid & 31;
    const int wo = (warp >> 2) << 6;
    const int wp = (warp & 3) << 5;
    const int gid = L >> 2, tid4 = L & 3;

    const uint32_t sbase = smem_u32(dynsm);
    const int aRow = wo + (L & 15);
    const int aCol = (L >> 4) << 3;
    const int xRow = L & 15;
    const int xCol = wp + ((L >> 4) << 3);

    int wRow[4], wJ[4], xKK[4], xJ[4];
    #pragma unroll
    for (int i = 0; i < 4; i++) {
        int e = tid + i * 256;
        wRow[i] = e >> 3; wJ[i] = e & 7;
        xKK[i] = e >> 4; xJ[i] = e & 15;
    }

    float acc[4][4][4];
    #pragma unroll
    for (int mt = 0; mt < 4; mt++)
        #pragma unroll
        for (int nt = 0; nt < 4; nt++)
            #pragma unroll
            for (int r = 0; r < 4; r++) acc[mt][nt][r] = 0.f;

    auto load_chunk = [&](int c, int stg) {
        int icg = c / 9;
        int tap = c - icg * 9;
        int dwi = tap % 3;
        int dh56 = (tap / 3 - 1) * HW_;
        uint32_t sb = sbase + (uint32_t)stg * (STG_ELEMS * 2);
        #pragma unroll
        for (int i = 0; i < 4; i++) {
            const unsigned short* srcw = g_wmix
                + ((size_t)(bb * O_ + o0 + wRow[i])) * KTOT
                + tap * 256 + icg * 64 + wJ[i] * 8;
            CP16(sb + 2u * (wRow[i] * SW_ROW + wJ[i] * 8), srcw);
            size_t plane = (size_t)((bb * 3 + dwi) * C_ + icg * 64 + xKK[i]);
            const unsigned short* srcx = g_xs + plane * PSTR + GUARD + n0 + dh56 + xJ[i] * 8;
            CP16(sb + 2u * (SW_STG + xKK[i] * SX_ROW + xJ[i] * 8), srcx);
        }
    };

    load_chunk(0, 0); CP_COMMIT();
    load_chunk(1, 1); CP_COMMIT();

    int stage = 0;
    for (int c = 0; c < NCHUNK; c++) {
        if (c < NCHUNK - 1) { CP_WAIT(1); } else { CP_WAIT(0); }
        __syncthreads();
        if (c + 2 < NCHUNK) {
            int s2 = stage + 2; if (s2 >= NSTG) s2 -= NSTG;
            load_chunk(c + 2, s2);
            CP_COMMIT();
        }

        const uint32_t sb = sbase + (uint32_t)stage * (STG_ELEMS * 2);
        #pragma unroll
        for (int ks = 0; ks < 4; ks++) {
            uint32_t A[4][4], Bh[2][4];
            #pragma unroll
            for (int mt = 0; mt < 4; mt++) {
                uint32_t a = sb + 2u * ((aRow + mt * 16) * SW_ROW + ks * 16 + aCol);
                ldsm4(A[mt], a);
            }
            #pragma unroll
            for (int np = 0; np < 2; np++) {
                uint32_t a = sb + 2u * (SW_STG + (ks * 16 + xRow) * SX_ROW + xCol + np * 16);
                ldsm4t(Bh[np], a);
            }
            #pragma unroll
            for (int mt = 0; mt < 4; mt++)
                #pragma unroll
                for (int nt = 0; nt < 4; nt++)
                    mma_f16(acc[mt][nt], A[mt], &Bh[nt >> 1][(nt & 1) * 2]);
        }
        stage = stage + 1; if (stage >= NSTG) stage -= NSTG;
    }

    #pragma unroll
    for (int mt = 0; mt < 4; mt++) {
        #pragma unroll
        for (int nt = 0; nt < 4; nt++) {
            int o = o0 + wo + mt * 16 + gid;
            int pix = n0 + wp + nt * 8 + tid4 * 2;
            if (pix < NPIX) {
                size_t base = ((size_t)(bb * O_ + o)) * NPIX + pix;
                *(float2*)&out[base] = make_float2(acc[mt][nt][0], acc[mt][nt][1]);
                *(float2*)&out[base + (size_t)8 * NPIX] = make_float2(acc[mt][nt][2], acc[mt][nt][3]);
            }
        }
    }
}

extern "C" void kernel_launch(void* const* d_in, const int* in_sizes, int n_in,
                              void* d_out, int out_size) {
    const float* x    = (const float*)d_in[0];
    const float* kern = (const float*)d_in[1];
    const float* w1   = (const float*)d_in[2];
    const float* b1   = (const float*)d_in[3];
    const float* w2   = (const float*)d_in[4];
    const float* b2   = (const float*)d_in[5];
    float* out = (float*)d_out;

    cudaFuncSetAttribute(conv_kernel, cudaFuncAttributeMaxDynamicSharedMemorySize, SMEM_BYTES);
    cudaFuncSetAttribute(mix_kernel, cudaFuncAttributeMaxDynamicSharedMemorySize, MIX_SMEM);

    split_pool_kernel<<<dim3(C_, B_), 256>>>(x);
    mlp_kernel<<<1, 256>>>(w1, b1, w2, b2);
    mix_kernel<<<O_, 256, MIX_SMEM>>>(kern);
    conv_kernel<<<dim3(GRIDX, 2, B_), 256, SMEM_BYTES>>>(out);
}

// round 12
// speedup vs baseline: 1.3445x; 1.2176x over previous
#include <cuda_runtime.h>
#include <cuda_bf16.h>
#include <cuda_fp16.h>
#include <cstdint>

// ---------------- dims ----------------
#define B_    16
#define C_    256
#define O_    256
#define HW_   56
#define NPIX  3136
#define NK    8
#define HID   64
#define NKEL  589824          // 256*256*9 per bank
#define NT    784             // 28*28 winograd tiles
#define NTP   896             // padded tiles (7*128)
#define NXI   16              // 4x4 transform points

#define NCHUNK2 4             // K=256 in chunks of 64
#define NSTG   3

// GEMM smem (fp16 units) — identical geometry to the proven conv kernel
#define SW_ROW   72
#define SX_ROW   136
#define SW_STG   (128 * SW_ROW)               // 9216
#define SX_STG   (64 * SX_ROW)                // 8704
#define STG_ELEMS (SW_STG + SX_STG)           // 17920
#define SMEM_BYTES (NSTG * STG_ELEMS * 2)     // 107520
#define MIX_SMEM  (8 * 2304 * 4 + 512)        // 74240

__device__ float g_pooled[B_ * C_];
__device__ float g_alphas[B_ * NK];
// V: [b*16+xi][ic][NTP] fp16   (input transform)
__device__ __align__(16) unsigned short g_V[(size_t)B_ * NXI * C_ * NTP];
// U: [b*16+xi][o][ic] fp16     (transformed mixed weights)
__device__ __align__(16) unsigned short g_U[(size_t)B_ * NXI * O_ * C_];
// M: [b*16+xi][o][NTP] fp16    (GEMM output, pre-inverse)
__device__ __align__(16) unsigned short g_M[(size_t)B_ * NXI * O_ * NTP];

// ---------------- asm helpers ----------------
__device__ __forceinline__ uint32_t smem_u32(const void* p) {
    uint32_t a;
    asm("{ .reg .u64 t; cvta.to.shared.u64 t, %1; cvt.u32.u64 %0, t; }" : "=r"(a) : "l"(p));
    return a;
}
#define CP16(dst, src) asm volatile("cp.async.cg.shared.global [%0], [%1], 16;" :: "r"(dst), "l"(src))
#define CP_COMMIT()    asm volatile("cp.async.commit_group;" ::: "memory")
#define CP_WAIT(n)     asm volatile("cp.async.wait_group %0;" :: "n"(n) : "memory")

__device__ __forceinline__ void ldsm4(uint32_t* r, uint32_t a) {
    asm volatile("ldmatrix.sync.aligned.m8n8.x4.shared.b16 {%0,%1,%2,%3}, [%4];"
                 : "=r"(r[0]), "=r"(r[1]), "=r"(r[2]), "=r"(r[3]) : "r"(a));
}
__device__ __forceinline__ void ldsm4t(uint32_t* r, uint32_t a) {
    asm volatile("ldmatrix.sync.aligned.m8n8.x4.trans.shared.b16 {%0,%1,%2,%3}, [%4];"
                 : "=r"(r[0]), "=r"(r[1]), "=r"(r[2]), "=r"(r[3]) : "r"(a));
}
__device__ __forceinline__ void mma_f16(float* d, const uint32_t* a, const uint32_t* b) {
    asm volatile("mma.sync.aligned.m16n8k16.row.col.f32.f16.f16.f32 "
                 "{%0,%1,%2,%3}, {%4,%5,%6,%7}, {%8,%9}, {%0,%1,%2,%3};"
                 : "+f"(d[0]), "+f"(d[1]), "+f"(d[2]), "+f"(d[3])
                 : "r"(a[0]), "r"(a[1]), "r"(a[2]), "r"(a[3]), "r"(b[0]), "r"(b[1]));
}
__device__ __forceinline__ uint32_t h2u(float a, float b) {
    __half2 h = __floats2half2_rn(a, b);
    return *(uint32_t*)&h;
}

// ---------------- Kernel 1: input transform V = B^T d B (+pool fused) ----------
__global__ void __launch_bounds__(256)
inputT_kernel(const float* __restrict__ x) {
    const int ic = blockIdx.x, b = blockIdx.y;
    __shared__ float sp[NPIX];
    __shared__ float red[8];
    const float4* xp = (const float4*)(x + ((size_t)(b * C_ + ic)) * NPIX);
    float s = 0.f;
    for (int i = threadIdx.x; i < NPIX / 4; i += 256) {
        float4 v = xp[i];
        *(float4*)&sp[i * 4] = v;
        s += (v.x + v.y) + (v.z + v.w);
    }
    #pragma unroll
    for (int o = 16; o > 0; o >>= 1) s += __shfl_xor_sync(0xffffffffu, s, o);
    if ((threadIdx.x & 31) == 0) red[threadIdx.x >> 5] = s;
    __syncthreads();
    if (threadIdx.x < 8) {
        s = red[threadIdx.x];
        #pragma unroll
        for (int o = 4; o > 0; o >>= 1) s += __shfl_xor_sync(0xffu, s, o);
        if (threadIdx.x == 0) g_pooled[b * C_ + ic] = s * (1.0f / NPIX);
    }

    const size_t vbase = ((size_t)(b * NXI)) * C_ * NTP + (size_t)ic * NTP;

    // tile pairs: t0 = 2p, tiles (ty, tx0) and (ty, tx0+1); pairs never cross rows (28 even)
    for (int p = threadIdx.x; p < NT / 2; p += 256) {
        int t0 = p * 2;
        int ty = t0 / 28, tx0 = t0 % 28;
        int r0 = 2 * ty - 1, c0 = 2 * tx0 - 1;
        float d[4][6];
        #pragma unroll
        for (int i = 0; i < 4; i++) {
            int r = r0 + i;
            bool rv = (r >= 0 && r < HW_);
            #pragma unroll
            for (int j = 0; j < 6; j++) {
                int c = c0 + j;
                d[i][j] = (rv && c >= 0 && c < HW_) ? sp[r * HW_ + c] : 0.f;
            }
        }
        float V0[16], V1[16];
        #pragma unroll
        for (int tt = 0; tt < 2; tt++) {
            int jo = 2 * tt;
            float tr[4][4];
            #pragma unroll
            for (int c = 0; c < 4; c++) {
                tr[0][c] = d[0][jo + c] - d[2][jo + c];
                tr[1][c] = d[1][jo + c] + d[2][jo + c];
                tr[2][c] = d[2][jo + c] - d[1][jo + c];
                tr[3][c] = d[1][jo + c] - d[3][jo + c];
            }
            float* V = tt ? V1 : V0;
            #pragma unroll
            for (int r = 0; r < 4; r++) {
                V[r * 4 + 0] = tr[r][0] - tr[r][2];
                V[r * 4 + 1] = tr[r][1] + tr[r][2];
                V[r * 4 + 2] = tr[r][2] - tr[r][1];
                V[r * 4 + 3] = tr[r][1] - tr[r][3];
            }
        }
        #pragma unroll
        for (int xi = 0; xi < 16; xi++) {
            size_t idx = vbase + (size_t)xi * (C_ * NTP) + t0;
            *(uint32_t*)&g_V[idx] = h2u(V0[xi], V1[xi]);
        }
    }
    // zero the pad region t in [784, 896)
    for (int p = threadIdx.x; p < (NTP - NT) / 2; p += 256) {
        int t0 = NT + p * 2;
        #pragma unroll
        for (int xi = 0; xi < 16; xi++) {
            size_t idx = vbase + (size_t)xi * (C_ * NTP) + t0;
            *(uint32_t*)&g_V[idx] = 0u;
        }
    }
}

// ---------------- Kernel 2: MLP + softmax ----------------
__global__ void mlp_kernel(const float* __restrict__ w1, const float* __restrict__ b1,
                           const float* __restrict__ w2, const float* __restrict__ b2) {
    __shared__ float sp[B_ * C_];
    __shared__ float sh[B_ * HID];
    __shared__ float sc[B_ * NK];
    int tid = threadIdx.x;
    for (int i = tid; i < B_ * C_; i += 256) sp[i] = g_pooled[i];
    __syncthreads();
    for (int t = tid; t < B_ * HID; t += 256) {
        int b = t >> 6, j = t & 63;
        float s = b1[j];
        #pragma unroll 8
        for (int c = 0; c < C_; c++) s = fmaf(sp[b * C_ + c], w1[c * HID + j], s);
        sh[t] = fmaxf(s, 0.f);
    }
    __syncthreads();
    if (tid < B_ * NK) {
        int b = tid >> 3, k = tid & 7;
        float s = b2[k];
        #pragma unroll
        for (int j = 0; j < HID; j++) s = fmaf(sh[b * HID + j], w2[j * NK + k], s);
        sc[tid] = s;
    }
    __syncthreads();
    if (tid < B_) {
        float m = -1e30f;
        #pragma unroll
        for (int k = 0; k < NK; k++) m = fmaxf(m, sc[tid * NK + k]);
        float e[NK], sum = 0.f;
        #pragma unroll
        for (int k = 0; k < NK; k++) { e[k] = __expf(sc[tid * NK + k] - m); sum += e[k]; }
        float inv = 1.0f / sum;
        #pragma unroll
        for (int k = 0; k < NK; k++) g_alphas[tid * NK + k] = e[k] * inv;
    }
}

// ---------------- Kernel 3: weight mix + transform U = G g G^T ----------------
extern __shared__ float mixsm[];
__global__ void mixU_kernel(const float* __restrict__ kern) {
    float* sv = mixsm;                    // [8][2304]
    float* sal = mixsm + 8 * 2304;        // [128]
    const int o = blockIdx.x, tid = threadIdx.x;
    if (tid < B_ * NK) sal[tid] = g_alphas[tid];
    #pragma unroll
    for (int k = 0; k < 8; k++)
        for (int i = tid; i < 2304; i += 256)
            sv[k * 2304 + i] = kern[(size_t)k * NKEL + (size_t)o * 2304 + i];
    __syncthreads();

    const int ic = tid;   // one ic per thread
    #pragma unroll
    for (int b = 0; b < B_; b++) {
        float g[3][3];
        #pragma unroll
        for (int r = 0; r < 3; r++)
            #pragma unroll
            for (int c = 0; c < 3; c++) {
                float sum = 0.f;
                #pragma unroll
                for (int k = 0; k < 8; k++)
                    sum = fmaf(sal[b * NK + k], sv[k * 2304 + ic * 9 + r * 3 + c], sum);
                g[r][c] = sum;
            }
        float q[4][3];
        #pragma unroll
        for (int c = 0; c < 3; c++) {
            q[0][c] = g[0][c];
            q[1][c] = 0.5f * (g[0][c] + g[1][c] + g[2][c]);
            q[2][c] = 0.5f * (g[0][c] - g[1][c] + g[2][c]);
            q[3][c] = g[2][c];
        }
        #pragma unroll
        for (int r = 0; r < 4; r++) {
            float U0 = q[r][0];
            float U1 = 0.5f * (q[r][0] + q[r][1] + q[r][2]);
            float U2 = 0.5f * (q[r][0] - q[r][1] + q[r][2]);
            float U3 = q[r][2];
            int xibase = r * 4;
            size_t base = ((size_t)(b * NXI) * O_ + o) * C_ + ic;
            g_U[base + (size_t)(xibase + 0) * (O_ * C_)] = __half_as_ushort(__float2half_rn(U0));
            g_U[base + (size_t)(xibase + 1) * (O_ * C_)] = __half_as_ushort(__float2half_rn(U1));
            g_U[base + (size_t)(xibase + 2) * (O_ * C_)] = __half_as_ushort(__float2half_rn(U2));
            g_U[base + (size_t)(xibase + 3) * (O_ * C_)] = __half_as_ushort(__float2half_rn(U3));
        }
    }
}

// ---------------- Kernel 4: batched GEMM M[bxi] = U[bxi] * V[bxi] ----------------
extern __shared__ __align__(16) unsigned short dynsm[];

__global__ void __launch_bounds__(256, 2)
wino_gemm(int dummy) {
    const int tid = threadIdx.x;
    const int n0 = blockIdx.x * 128;      // tile-column base (0..768)
    const int o0 = blockIdx.y * 128;
    const int bxi = blockIdx.z;           // 0..255

    const int warp = tid >> 5, L = tid & 31;
    const int wo = (warp >> 2) << 6;
    const int wp = (warp & 3) << 5;
    const int gid = L >> 2, tid4 = L & 3;

    const uint32_t sbase = smem_u32(dynsm);
    const int aRow = wo + (L & 15);
    const int aCol = (L >> 4) << 3;
    const int xRow = L & 15;
    const int xCol = wp + ((L >> 4) << 3);

    int wRow[4], wJ[4], xKK[4], xJ[4];
    #pragma unroll
    for (int i = 0; i < 4; i++) {
        int e = tid + i * 256;
        wRow[i] = e >> 3; wJ[i] = e & 7;
        xKK[i] = e >> 4; xJ[i] = e & 15;
    }

    float acc[4][4][4];
    #pragma unroll
    for (int mt = 0; mt < 4; mt++)
        #pragma unroll
        for (int nt = 0; nt < 4; nt++)
            #pragma unroll
            for (int r = 0; r < 4; r++) acc[mt][nt][r] = 0.f;

    const unsigned short* Ub = g_U + (size_t)bxi * (O_ * C_);
    const unsigned short* Vb = g_V + (size_t)bxi * (C_ * NTP);

    auto load_chunk = [&](int c, int stg) {
        uint32_t sb = sbase + (uint32_t)stg * (STG_ELEMS * 2);
        #pragma unroll
        for (int i = 0; i < 4; i++) {
            const unsigned short* srcw = Ub + (size_t)(o0 + wRow[i]) * C_ + c * 64 + wJ[i] * 8;
            CP16(sb + 2u * (wRow[i] * SW_ROW + wJ[i] * 8), srcw);
            const unsigned short* srcx = Vb + (size_t)(c * 64 + xKK[i]) * NTP + n0 + xJ[i] * 8;
            CP16(sb + 2u * (SW_STG + xKK[i] * SX_ROW + xJ[i] * 8), srcx);
        }
    };

    load_chunk(0, 0); CP_COMMIT();
    load_chunk(1, 1); CP_COMMIT();

    int stage = 0;
    for (int c = 0; c < NCHUNK2; c++) {
        if (c < NCHUNK2 - 1) { CP_WAIT(1); } else { CP_WAIT(0); }
        __syncthreads();
        if (c + 2 < NCHUNK2) {
            int s2 = stage + 2; if (s2 >= NSTG) s2 -= NSTG;
            load_chunk(c + 2, s2);
            CP_COMMIT();
        }

        const uint32_t sb = sbase + (uint32_t)stage * (STG_ELEMS * 2);
        #pragma unroll
        for (int ks = 0; ks < 4; ks++) {
            uint32_t A[4][4], Bh[2][4];
            #pragma unroll
            for (int mt = 0; mt < 4; mt++) {
                uint32_t a = sb + 2u * ((aRow + mt * 16) * SW_ROW + ks * 16 + aCol);
                ldsm4(A[mt], a);
            }
            #pragma unroll
            for (int np = 0; np < 2; np++) {
                uint32_t a = sb + 2u * (SW_STG + (ks * 16 + xRow) * SX_ROW + xCol + np * 16);
                ldsm4t(Bh[np], a);
            }
            #pragma unroll
            for (int mt = 0; mt < 4; mt++)
                #pragma unroll
                for (int nt = 0; nt < 4; nt++)
                    mma_f16(acc[mt][nt], A[mt], &Bh[nt >> 1][(nt & 1) * 2]);
        }
        stage = stage + 1; if (stage >= NSTG) stage -= NSTG;
    }

    // epilogue: M fp16. acc pairs (0,1)->row o, (2,3)->row o+8  [THE FIX]
    unsigned short* Mb = g_M + (size_t)bxi * (O_ * NTP);
    #pragma unroll
    for (int mt = 0; mt < 4; mt++) {
        #pragma unroll
        for (int nt = 0; nt < 4; nt++) {
            int o = o0 + wo + mt * 16 + gid;
            int pix = n0 + wp + nt * 8 + tid4 * 2;
            *(uint32_t*)&Mb[(size_t)o * NTP + pix]       = h2u(acc[mt][nt][0], acc[mt][nt][1]);
            *(uint32_t*)&Mb[(size_t)(o + 8) * NTP + pix] = h2u(acc[mt][nt][2], acc[mt][nt][3]);
        }
    }
}

// ---------------- Kernel 5: inverse transform Y = A^T m A -> out ----------------
__global__ void __launch_bounds__(256)
inverseT_kernel(float* __restrict__ out) {
    const int o = blockIdx.x, b = blockIdx.y;
    const size_t mbase = ((size_t)(b * NXI)) * O_ * NTP + (size_t)o * NTP;
    const size_t obase = ((size_t)(b * O_ + o)) * NPIX;

    for (int p = threadIdx.x; p < NT / 2; p += 256) {
        int t0 = p * 2;
        int ty = t0 / 28, tx0 = t0 % 28;
        float m0[16], m1[16];
        #pragma unroll
        for (int xi = 0; xi < 16; xi++) {
            uint32_t v = *(const uint32_t*)&g_M[mbase + (size_t)xi * (O_ * NTP) + t0];
            __half2 h = *(__half2*)&v;
            m0[xi] = __low2float(h);
            m1[xi] = __high2float(h);
        }
        float Y0[2][2], Y1[2][2];
        #pragma unroll
        for (int tt = 0; tt < 2; tt++) {
            float* m = tt ? m1 : m0;
            float sr[2][4];
            #pragma unroll
            for (int c = 0; c < 4; c++) {
                sr[0][c] = m[0 * 4 + c] + m[1 * 4 + c] + m[2 * 4 + c];
                sr[1][c] = m[1 * 4 + c] - m[2 * 4 + c] - m[3 * 4 + c];
            }
            float (*Y)[2] = tt ? Y1 : Y0;
            #pragma unroll
            for (int r = 0; r < 2; r++) {
                Y[r][0] = sr[r][0] + sr[r][1] + sr[r][2];
                Y[r][1] = sr[r][1] - sr[r][2] - sr[r][3];
            }
        }
        int orow = 2 * ty, ocol = 2 * tx0;
        size_t pbase = obase + (size_t)orow * HW_ + ocol;
        *(float2*)&out[pbase]            = make_float2(Y0[0][0], Y0[0][1]);
        *(float2*)&out[pbase + 2]        = make_float2(Y1[0][0], Y1[0][1]);
        *(float2*)&out[pbase + HW_]      = make_float2(Y0[1][0], Y0[1][1]);
        *(float2*)&out[pbase + HW_ + 2]  = make_float2(Y1[1][0], Y1[1][1]);
    }
}

extern "C" void kernel_launch(void* const* d_in, const int* in_sizes, int n_in,
                              void* d_out, int out_size) {
    const float* x    = (const float*)d_in[0];
    const float* kern = (const float*)d_in[1];
    const float* w1   = (const float*)d_in[2];
    const float* b1   = (const float*)d_in[3];
    const float* w2   = (const float*)d_in[4];
    const float* b2   = (const float*)d_in[5];
    float* out = (float*)d_out;

    cudaFuncSetAttribute(wino_gemm, cudaFuncAttributeMaxDynamicSharedMemorySize, SMEM_BYTES);
    cudaFuncSetAttribute(mixU_kernel, cudaFuncAttributeMaxDynamicSharedMemorySize, MIX_SMEM);

    inputT_kernel<<<dim3(C_, B_), 256>>>(x);
    mlp_kernel<<<1, 256>>>(w1, b1, w2, b2);
    mixU_kernel<<<O_, 256, MIX_SMEM>>>(kern);
    wino_gemm<<<dim3(7, 2, B_ * NXI), 256, SMEM_BYTES>>>(0);
    inverseT_kernel<<<dim3(O_, B_), 256>>>(out);
}